// round 1
// baseline (speedup 1.0000x reference)
#include <cuda_runtime.h>
#include <cuda_bf16.h>
#include <math.h>

// Problem constants
#define LQ 4096
#define DIM 2048
#define NH 8
#define NKVH 2
#define HD 256
#define WIN 512

// Scratch (static device allocations are allowed)
__device__ float g_q[(size_t)LQ * NH * HD];
__device__ float g_k[(size_t)LQ * NKVH * HD];
__device__ float g_v[(size_t)LQ * NKVH * HD];
__device__ float g_attn[(size_t)LQ * NH * HD];

// ---------------------------------------------------------------------------
// SGEMM: C[M,N] = A[M,K] * B[K,N], all row-major fp32.
// 64x64 block tile, 16 K-tile, 256 threads, 4x4 per-thread micro-tile.
// M,N multiples of 64; K multiple of 16 (true for all our shapes).
// ---------------------------------------------------------------------------
__global__ __launch_bounds__(256) void sgemm64(const float* __restrict__ A,
                                               const float* __restrict__ B,
                                               float* __restrict__ C,
                                               int M, int N, int K) {
    __shared__ float As[16][64];
    __shared__ float Bs[16][64];

    int tid = threadIdx.x;
    int tx = tid & 15;      // 0..15 (N micro)
    int ty = tid >> 4;      // 0..15 (M micro)
    int m0 = blockIdx.y * 64;
    int n0 = blockIdx.x * 64;

    // A tile load mapping: 64 rows x 16 cols, float4 per thread
    int ar = tid >> 2;            // 0..63
    int ac = (tid & 3) * 4;       // 0,4,8,12
    // B tile load mapping: 16 rows x 64 cols, float4 per thread
    int br = tid >> 4;            // 0..15
    int bc = (tid & 15) * 4;      // 0..60

    const float* Aptr = A + (size_t)(m0 + ar) * K + ac;
    const float* Bptr = B + (size_t)br * N + n0 + bc;

    float acc[4][4];
#pragma unroll
    for (int i = 0; i < 4; i++)
#pragma unroll
        for (int j = 0; j < 4; j++) acc[i][j] = 0.0f;

    for (int k0 = 0; k0 < K; k0 += 16) {
        float4 av = *(const float4*)Aptr;
        float4 bv = *(const float4*)Bptr;
        As[ac + 0][ar] = av.x;
        As[ac + 1][ar] = av.y;
        As[ac + 2][ar] = av.z;
        As[ac + 3][ar] = av.w;
        *(float4*)&Bs[br][bc] = bv;
        __syncthreads();
#pragma unroll
        for (int kk = 0; kk < 16; kk++) {
            float4 a = *(const float4*)&As[kk][ty * 4];
            float4 b = *(const float4*)&Bs[kk][tx * 4];
            acc[0][0] += a.x * b.x; acc[0][1] += a.x * b.y; acc[0][2] += a.x * b.z; acc[0][3] += a.x * b.w;
            acc[1][0] += a.y * b.x; acc[1][1] += a.y * b.y; acc[1][2] += a.y * b.z; acc[1][3] += a.y * b.w;
            acc[2][0] += a.z * b.x; acc[2][1] += a.z * b.y; acc[2][2] += a.z * b.z; acc[2][3] += a.z * b.w;
            acc[3][0] += a.w * b.x; acc[3][1] += a.w * b.y; acc[3][2] += a.w * b.z; acc[3][3] += a.w * b.w;
        }
        __syncthreads();
        Aptr += 16;
        Bptr += (size_t)16 * N;
    }

#pragma unroll
    for (int i = 0; i < 4; i++) {
        float4 o;
        o.x = acc[i][0]; o.y = acc[i][1]; o.z = acc[i][2]; o.w = acc[i][3];
        *(float4*)&C[(size_t)(m0 + ty * 4 + i) * N + n0 + tx * 4] = o;
    }
}

// ---------------------------------------------------------------------------
// RMSNorm (+ optional scale) (+ optional RoPE, rope_fraction = 1.0)
// One block per (token, head), 256 threads = head_dim.
// ---------------------------------------------------------------------------
__global__ __launch_bounds__(256) void norm_rope_kernel(float* __restrict__ buf,
                                                        int nheads,
                                                        const float* __restrict__ scale,
                                                        const int* __restrict__ positions,
                                                        int do_rope) {
    int li = blockIdx.x;
    int h = blockIdx.y;
    int tid = threadIdx.x;
    float* p = buf + ((size_t)li * nheads + h) * HD;

    float x = p[tid];
    float ss = x * x;
#pragma unroll
    for (int o = 16; o; o >>= 1) ss += __shfl_xor_sync(0xffffffffu, ss, o);
    __shared__ float red[8];
    if ((tid & 31) == 0) red[tid >> 5] = ss;
    __syncthreads();
    float tot = 0.0f;
#pragma unroll
    for (int i = 0; i < 8; i++) tot += red[i];
    float rstd = rsqrtf(tot * (1.0f / 256.0f) + 1e-6f);
    float xn = x * rstd;
    if (scale) xn *= scale[tid];

    if (!do_rope) {
        p[tid] = xn;
        return;
    }

    __shared__ float xs[256];
    xs[tid] = xn;
    __syncthreads();
    if (tid < 128) {
        int pos = positions[li];
        // timescale = 10000^(tid/128) = 2^(log2(10000)*tid/128)
        float ts = exp2f(13.287712379549449f * (float)tid * (1.0f / 128.0f));
        float su = (float)pos / ts;
        float s = sinf(su);
        float c = cosf(su);
        float x1 = xs[tid];
        float x2 = xs[tid + 128];
        p[tid] = x1 * c - x2 * s;
        p[tid + 128] = x2 * c + x1 * s;
    }
}

// ---------------------------------------------------------------------------
// Sliding-window attention. Block per (query, head), 256 threads.
// Scores via warp-parallel dot products, softmax in smem, V accumulation
// coalesced (thread = output dim).
// ---------------------------------------------------------------------------
__global__ __launch_bounds__(256) void attn_kernel() {
    int qi = blockIdx.x;
    int h = blockIdx.y;
    int kvh = h >> 2;  // H / KVH = 4
    int tid = threadIdx.x;
    int lane = tid & 31;
    int w = tid >> 5;

    __shared__ float qs[HD];
    __shared__ float sc[WIN];
    __shared__ float redm[8];
    __shared__ float reds[8];

    const float* qp = g_q + ((size_t)qi * NH + h) * HD;
    qs[tid] = qp[tid];
    __syncthreads();

    int j0 = qi - (WIN - 1);
    if (j0 < 0) j0 = 0;
    int nk = qi - j0 + 1;

    // scores
    for (int jj = w; jj < nk; jj += 8) {
        const float* kp = g_k + ((size_t)(j0 + jj) * NKVH + kvh) * HD;
        float s = 0.0f;
#pragma unroll
        for (int d = 0; d < HD; d += 32) s += qs[d + lane] * kp[d + lane];
#pragma unroll
        for (int o = 16; o; o >>= 1) s += __shfl_xor_sync(0xffffffffu, s, o);
        if (lane == 0) sc[jj] = s;
    }
    __syncthreads();

    // max
    float m = -1e30f;
    for (int jj = tid; jj < nk; jj += 256) m = fmaxf(m, sc[jj]);
#pragma unroll
    for (int o = 16; o; o >>= 1) m = fmaxf(m, __shfl_xor_sync(0xffffffffu, m, o));
    if (lane == 0) redm[w] = m;
    __syncthreads();
    m = redm[0];
#pragma unroll
    for (int i = 1; i < 8; i++) m = fmaxf(m, redm[i]);

    // exp + sum
    float ssum = 0.0f;
    for (int jj = tid; jj < nk; jj += 256) {
        float e = __expf(sc[jj] - m);
        sc[jj] = e;
        ssum += e;
    }
#pragma unroll
    for (int o = 16; o; o >>= 1) ssum += __shfl_xor_sync(0xffffffffu, ssum, o);
    if (lane == 0) reds[w] = ssum;
    __syncthreads();
    ssum = 0.0f;
#pragma unroll
    for (int i = 0; i < 8; i++) ssum += reds[i];
    float inv = 1.0f / ssum;

    // output: thread tid = output dim
    float acc = 0.0f;
    const float* vbase = g_v + ((size_t)j0 * NKVH + kvh) * HD + tid;
    for (int jj = 0; jj < nk; jj++) {
        acc += sc[jj] * vbase[(size_t)jj * (NKVH * HD)];
    }
    g_attn[((size_t)qi * NH + h) * HD + tid] = acc * inv;
}

// ---------------------------------------------------------------------------
extern "C" void kernel_launch(void* const* d_in, const int* in_sizes, int n_in,
                              void* d_out, int out_size) {
    const float* x = (const float*)d_in[0];
    const int* positions = (const int*)d_in[1];
    const float* Wq = (const float*)d_in[2];
    const float* Wk = (const float*)d_in[3];
    const float* Wv = (const float*)d_in[4];
    const float* Wo = (const float*)d_in[5];
    const float* q_scale = (const float*)d_in[6];
    const float* k_scale = (const float*)d_in[7];
    float* out = (float*)d_out;

    float *qb, *kb, *vb, *ab;
    cudaGetSymbolAddress((void**)&qb, g_q);
    cudaGetSymbolAddress((void**)&kb, g_k);
    cudaGetSymbolAddress((void**)&vb, g_v);
    cudaGetSymbolAddress((void**)&ab, g_attn);

    dim3 blk(256);

    // QKV projections
    sgemm64<<<dim3((NH * HD) / 64, LQ / 64), blk>>>(x, Wq, qb, LQ, NH * HD, DIM);
    sgemm64<<<dim3((NKVH * HD) / 64, LQ / 64), blk>>>(x, Wk, kb, LQ, NKVH * HD, DIM);
    sgemm64<<<dim3((NKVH * HD) / 64, LQ / 64), blk>>>(x, Wv, vb, LQ, NKVH * HD, DIM);

    // Norm + RoPE
    norm_rope_kernel<<<dim3(LQ, NH), blk>>>(qb, NH, q_scale, positions, 1);
    norm_rope_kernel<<<dim3(LQ, NKVH), blk>>>(kb, NKVH, k_scale, positions, 1);
    norm_rope_kernel<<<dim3(LQ, NKVH), blk>>>(vb, NKVH, (const float*)nullptr, positions, 0);

    // Attention
    attn_kernel<<<dim3(LQ, NH), blk>>>();

    // Output projection
    sgemm64<<<dim3(DIM / 64, LQ / 64), blk>>>(ab, Wo, out, LQ, DIM, NH * HD);
}

// round 2
// speedup vs baseline: 2.5022x; 2.5022x over previous
#include <cuda_runtime.h>
#include <cuda_bf16.h>
#include <math.h>

#define LQ 4096
#define DIM 2048
#define NH 8
#define NKVH 2
#define HD 256
#define WIN 512

__device__ float g_q[(size_t)LQ * NH * HD];
__device__ float g_k[(size_t)LQ * NKVH * HD];
__device__ float g_v[(size_t)LQ * NKVH * HD];
__device__ float g_attn[(size_t)LQ * NH * HD];

// ---------------------------------------------------------------------------
// SGEMM 128x128x16, double-buffered, 8x8 microtile, 256 threads.
// Supports up to 3 fused (B,C,N) targets selected by blockIdx.x range so that
// Wq/Wk/Wv run as one launch. M = gridDim.y*128, dims are exact multiples.
// ---------------------------------------------------------------------------
__global__ __launch_bounds__(256, 2) void sgemm128(
    const float* __restrict__ A, int K,
    const float* __restrict__ B0, float* __restrict__ C0, int N0, int t0,
    const float* __restrict__ B1, float* __restrict__ C1, int N1, int t1,
    const float* __restrict__ B2, float* __restrict__ C2, int N2) {
    __shared__ float As[2][16][132];
    __shared__ float Bs[2][16][132];

    int tid = threadIdx.x;
    int tx = tid & 15;
    int ty = tid >> 4;
    int m0 = blockIdx.y * 128;

    int bx = blockIdx.x;
    const float* B; float* C; int N; int n0;
    if (bx < t0)            { B = B0; C = C0; N = N0; n0 = bx * 128; }
    else if (bx < t0 + t1)  { B = B1; C = C1; N = N1; n0 = (bx - t0) * 128; }
    else                    { B = B2; C = C2; N = N2; n0 = (bx - t0 - t1) * 128; }

    // A tile: 128 rows x 16 cols; 2 float4 per thread
    int ar = tid >> 2;          // 0..63 (+64 for f=1)
    int ac = (tid & 3) * 4;     // 0,4,8,12
    // B tile: 16 rows x 128 cols; 2 float4 per thread
    int br = tid >> 5;          // 0..7 (+8 for f=1)
    int bc = (tid & 31) * 4;    // 0..124

    const float* Arow0 = A + (size_t)(m0 + ar) * K;
    const float* Arow1 = A + (size_t)(m0 + ar + 64) * K;
    const float* Brow0 = B + (size_t)br * N + n0;
    const float* Brow1 = B + (size_t)(br + 8) * N + n0;

    float acc[8][8];
#pragma unroll
    for (int i = 0; i < 8; i++)
#pragma unroll
        for (int j = 0; j < 8; j++) acc[i][j] = 0.0f;

    // preload tile 0
    {
        float4 a0 = *(const float4*)(Arow0 + ac);
        float4 a1 = *(const float4*)(Arow1 + ac);
        float4 b0 = *(const float4*)(Brow0 + bc);
        float4 b1 = *(const float4*)(Brow1 + bc);
        As[0][ac + 0][ar] = a0.x; As[0][ac + 1][ar] = a0.y;
        As[0][ac + 2][ar] = a0.z; As[0][ac + 3][ar] = a0.w;
        As[0][ac + 0][ar + 64] = a1.x; As[0][ac + 1][ar + 64] = a1.y;
        As[0][ac + 2][ar + 64] = a1.z; As[0][ac + 3][ar + 64] = a1.w;
        *(float4*)&Bs[0][br][bc] = b0;
        *(float4*)&Bs[0][br + 8][bc] = b1;
    }
    __syncthreads();

    int ntiles = K >> 4;
    for (int kt = 0; kt < ntiles; kt++) {
        int cur = kt & 1, nxt = cur ^ 1;
        float4 pa0, pa1, pb0, pb1;
        bool more = (kt + 1) < ntiles;
        if (more) {
            int kc = (kt + 1) << 4;
            pa0 = *(const float4*)(Arow0 + kc + ac);
            pa1 = *(const float4*)(Arow1 + kc + ac);
            pb0 = *(const float4*)(Brow0 + (size_t)kc * N + bc);
            pb1 = *(const float4*)(Brow1 + (size_t)kc * N + bc);
        }
#pragma unroll
        for (int kk = 0; kk < 16; kk++) {
            float4 a0 = *(const float4*)&As[cur][kk][ty * 4];
            float4 a1 = *(const float4*)&As[cur][kk][64 + ty * 4];
            float4 b0 = *(const float4*)&Bs[cur][kk][tx * 4];
            float4 b1 = *(const float4*)&Bs[cur][kk][64 + tx * 4];
            float am[8] = {a0.x, a0.y, a0.z, a0.w, a1.x, a1.y, a1.z, a1.w};
            float bn[8] = {b0.x, b0.y, b0.z, b0.w, b1.x, b1.y, b1.z, b1.w};
#pragma unroll
            for (int i = 0; i < 8; i++)
#pragma unroll
                for (int j = 0; j < 8; j++) acc[i][j] += am[i] * bn[j];
        }
        if (more) {
            As[nxt][ac + 0][ar] = pa0.x; As[nxt][ac + 1][ar] = pa0.y;
            As[nxt][ac + 2][ar] = pa0.z; As[nxt][ac + 3][ar] = pa0.w;
            As[nxt][ac + 0][ar + 64] = pa1.x; As[nxt][ac + 1][ar + 64] = pa1.y;
            As[nxt][ac + 2][ar + 64] = pa1.z; As[nxt][ac + 3][ar + 64] = pa1.w;
            *(float4*)&Bs[nxt][br][bc] = pb0;
            *(float4*)&Bs[nxt][br + 8][bc] = pb1;
        }
        __syncthreads();
    }

#pragma unroll
    for (int i2 = 0; i2 < 2; i2++)
#pragma unroll
        for (int i = 0; i < 4; i++) {
            int m = m0 + i2 * 64 + ty * 4 + i;
            float4 o0, o1;
            o0.x = acc[i2 * 4 + i][0]; o0.y = acc[i2 * 4 + i][1];
            o0.z = acc[i2 * 4 + i][2]; o0.w = acc[i2 * 4 + i][3];
            o1.x = acc[i2 * 4 + i][4]; o1.y = acc[i2 * 4 + i][5];
            o1.z = acc[i2 * 4 + i][6]; o1.w = acc[i2 * 4 + i][7];
            *(float4*)&C[(size_t)m * N + n0 + tx * 4] = o0;
            *(float4*)&C[(size_t)m * N + n0 + 64 + tx * 4] = o1;
        }
}

// ---------------------------------------------------------------------------
// RMSNorm (+scale) (+RoPE)
// ---------------------------------------------------------------------------
__global__ __launch_bounds__(256) void norm_rope_kernel(float* __restrict__ buf,
                                                        int nheads,
                                                        const float* __restrict__ scale,
                                                        const int* __restrict__ positions,
                                                        int do_rope) {
    int li = blockIdx.x;
    int h = blockIdx.y;
    int tid = threadIdx.x;
    float* p = buf + ((size_t)li * nheads + h) * HD;

    float x = p[tid];
    float ss = x * x;
#pragma unroll
    for (int o = 16; o; o >>= 1) ss += __shfl_xor_sync(0xffffffffu, ss, o);
    __shared__ float red[8];
    if ((tid & 31) == 0) red[tid >> 5] = ss;
    __syncthreads();
    float tot = 0.0f;
#pragma unroll
    for (int i = 0; i < 8; i++) tot += red[i];
    float rstd = rsqrtf(tot * (1.0f / 256.0f) + 1e-6f);
    float xn = x * rstd;
    if (scale) xn *= scale[tid];

    if (!do_rope) { p[tid] = xn; return; }

    __shared__ float xs[256];
    xs[tid] = xn;
    __syncthreads();
    if (tid < 128) {
        int pos = positions[li];
        float ts = exp2f(13.287712379549449f * (float)tid * (1.0f / 128.0f));
        float su = (float)pos / ts;
        float s = sinf(su);
        float c = cosf(su);
        float x1 = xs[tid];
        float x2 = xs[tid + 128];
        p[tid] = x1 * c - x2 * s;
        p[tid + 128] = x2 * c + x1 * s;
    }
}

// ---------------------------------------------------------------------------
// Flash-style sliding-window attention.
// Block = (64-query tile, head). 256 threads, 8 warps. K-tiles of 32 keys.
// Stage A: S = Q*K^T (16x16 thread grid, 4q x 2k microtile) -> smem.
// Stage B: online softmax + P*V; warp owns 8 queries, lane owns 8 dims.
// ---------------------------------------------------------------------------
#define QT 64
#define KT 32
#define QPAD 260
#define KTPAD 34
#define SPAD 33

__global__ __launch_bounds__(256) void attn_kernel() {
    extern __shared__ float sm[];
    float* Qs = sm;                       // [64][260]
    float* Kt = Qs + QT * QPAD;           // [256][34] transposed
    float* Vs = Kt + HD * KTPAD;          // [32][260]
    float* Ss = Vs + KT * QPAD;           // [64][33]

    int q0 = blockIdx.x * QT;
    int h = blockIdx.y;
    int kvh = h >> 2;
    int tid = threadIdx.x;
    int lane = tid & 31;
    int w = tid >> 5;
    int tx = tid & 15;       // stage A: key pair
    int ty = tid >> 4;       // stage A: query quad

    // Load Q tile (64 x 256)
#pragma unroll
    for (int f = 0; f < 16; f++) {
        int id = f * 256 + tid;
        int q = id >> 6;
        int d = (id & 63) * 4;
        float4 v = *(const float4*)&g_q[((size_t)(q0 + q) * NH + h) * HD + d];
        *(float4*)&Qs[q * QPAD + d] = v;
    }

    float acc[8][8];
    float m8[8], l8[8];
#pragma unroll
    for (int i = 0; i < 8; i++) {
        m8[i] = -1e30f; l8[i] = 0.0f;
#pragma unroll
        for (int j = 0; j < 8; j++) acc[i][j] = 0.0f;
    }

    int kt0 = q0 - WIN;        // first tile start (multiple of 32); may be <0
    if (kt0 < 0) kt0 = 0;
    int ktend = q0 + QT;       // exclusive

    __syncthreads();

    for (int kt = kt0; kt < ktend; kt += KT) {
        // ---- load K (transposed) and V tiles ----
        {
            int row = tid >> 3;               // 0..31
            int cb = (tid & 7) * 4;
            const float* kg = g_k + ((size_t)(kt + row) * NKVH + kvh) * HD;
#pragma unroll
            for (int f = 0; f < 8; f++) {
                int col = cb + f * 32;
                float4 v = *(const float4*)(kg + col);
                Kt[(col + 0) * KTPAD + row] = v.x;
                Kt[(col + 1) * KTPAD + row] = v.y;
                Kt[(col + 2) * KTPAD + row] = v.z;
                Kt[(col + 3) * KTPAD + row] = v.w;
            }
#pragma unroll
            for (int f = 0; f < 8; f++) {
                int id = f * 256 + tid;
                int r = id >> 6;
                int d = (id & 63) * 4;
                float4 v = *(const float4*)&g_v[((size_t)(kt + r) * NKVH + kvh) * HD + d];
                *(float4*)&Vs[r * QPAD + d] = v;
            }
        }
        __syncthreads();

        // ---- stage A: scores ----
        {
            int q4 = ty * 4;
            int k2 = tx * 2;
            float s[4][2];
#pragma unroll
            for (int i = 0; i < 4; i++) { s[i][0] = 0.f; s[i][1] = 0.f; }
            for (int d0 = 0; d0 < HD; d0 += 4) {
                float4 qv0 = *(const float4*)&Qs[(q4 + 0) * QPAD + d0];
                float4 qv1 = *(const float4*)&Qs[(q4 + 1) * QPAD + d0];
                float4 qv2 = *(const float4*)&Qs[(q4 + 2) * QPAD + d0];
                float4 qv3 = *(const float4*)&Qs[(q4 + 3) * QPAD + d0];
                float2 k0 = *(const float2*)&Kt[(d0 + 0) * KTPAD + k2];
                float2 k1 = *(const float2*)&Kt[(d0 + 1) * KTPAD + k2];
                float2 k2v = *(const float2*)&Kt[(d0 + 2) * KTPAD + k2];
                float2 k3 = *(const float2*)&Kt[(d0 + 3) * KTPAD + k2];
                float qa[4][4] = {{qv0.x, qv0.y, qv0.z, qv0.w},
                                  {qv1.x, qv1.y, qv1.z, qv1.w},
                                  {qv2.x, qv2.y, qv2.z, qv2.w},
                                  {qv3.x, qv3.y, qv3.z, qv3.w}};
                float kx[4] = {k0.x, k1.x, k2v.x, k3.x};
                float ky[4] = {k0.y, k1.y, k2v.y, k3.y};
#pragma unroll
                for (int dd = 0; dd < 4; dd++)
#pragma unroll
                    for (int i = 0; i < 4; i++) {
                        s[i][0] += qa[i][dd] * kx[dd];
                        s[i][1] += qa[i][dd] * ky[dd];
                    }
            }
#pragma unroll
            for (int i = 0; i < 4; i++)
#pragma unroll
                for (int j = 0; j < 2; j++) {
                    int qg = q0 + q4 + i;
                    int kg = kt + k2 + j;
                    bool ok = (kg <= qg) && (kg + WIN > qg);
                    Ss[(q4 + i) * SPAD + k2 + j] = ok ? s[i][j] : -1e30f;
                }
        }
        __syncthreads();

        // ---- stage B: online softmax + PV ----
        {
            float p8[8];
#pragma unroll
            for (int q8 = 0; q8 < 8; q8++) {
                int qrow = w * 8 + q8;
                int qg = q0 + qrow;
                int kg = kt + lane;
                float s = Ss[qrow * SPAD + lane];
                float mx = s;
#pragma unroll
                for (int o = 16; o; o >>= 1) mx = fmaxf(mx, __shfl_xor_sync(0xffffffffu, mx, o));
                float mn = fmaxf(m8[q8], mx);
                bool ok = (kg <= qg) && (kg + WIN > qg);
                float p = ok ? __expf(s - mn) : 0.0f;
                float sum = p;
#pragma unroll
                for (int o = 16; o; o >>= 1) sum += __shfl_xor_sync(0xffffffffu, sum, o);
                float sc = __expf(m8[q8] - mn);
                l8[q8] = l8[q8] * sc + sum;
                m8[q8] = mn;
#pragma unroll
                for (int j = 0; j < 8; j++) acc[q8][j] *= sc;
                p8[q8] = p;
            }
#pragma unroll
            for (int k = 0; k < KT; k++) {
                float4 v0 = *(const float4*)&Vs[k * QPAD + lane * 4];
                float4 v1 = *(const float4*)&Vs[k * QPAD + 128 + lane * 4];
#pragma unroll
                for (int q8 = 0; q8 < 8; q8++) {
                    float pk = __shfl_sync(0xffffffffu, p8[q8], k);
                    acc[q8][0] += pk * v0.x; acc[q8][1] += pk * v0.y;
                    acc[q8][2] += pk * v0.z; acc[q8][3] += pk * v0.w;
                    acc[q8][4] += pk * v1.x; acc[q8][5] += pk * v1.y;
                    acc[q8][6] += pk * v1.z; acc[q8][7] += pk * v1.w;
                }
            }
        }
        __syncthreads();
    }

    // write output
#pragma unroll
    for (int q8 = 0; q8 < 8; q8++) {
        int qg = q0 + w * 8 + q8;
        float inv = 1.0f / l8[q8];
        size_t base = ((size_t)qg * NH + h) * HD;
        float4 o0, o1;
        o0.x = acc[q8][0] * inv; o0.y = acc[q8][1] * inv;
        o0.z = acc[q8][2] * inv; o0.w = acc[q8][3] * inv;
        o1.x = acc[q8][4] * inv; o1.y = acc[q8][5] * inv;
        o1.z = acc[q8][6] * inv; o1.w = acc[q8][7] * inv;
        *(float4*)&g_attn[base + lane * 4] = o0;
        *(float4*)&g_attn[base + 128 + lane * 4] = o1;
    }
}

// ---------------------------------------------------------------------------
extern "C" void kernel_launch(void* const* d_in, const int* in_sizes, int n_in,
                              void* d_out, int out_size) {
    const float* x = (const float*)d_in[0];
    const int* positions = (const int*)d_in[1];
    const float* Wq = (const float*)d_in[2];
    const float* Wk = (const float*)d_in[3];
    const float* Wv = (const float*)d_in[4];
    const float* Wo = (const float*)d_in[5];
    const float* q_scale = (const float*)d_in[6];
    const float* k_scale = (const float*)d_in[7];
    float* out = (float*)d_out;

    float *qb, *kb, *vb, *ab;
    cudaGetSymbolAddress((void**)&qb, g_q);
    cudaGetSymbolAddress((void**)&kb, g_k);
    cudaGetSymbolAddress((void**)&vb, g_v);
    cudaGetSymbolAddress((void**)&ab, g_attn);

    static bool attr_set = false;
    if (!attr_set) {
        cudaFuncSetAttribute(attn_kernel, cudaFuncAttributeMaxDynamicSharedMemorySize,
                             (QT * QPAD + HD * KTPAD + KT * QPAD + QT * SPAD) * 4);
        attr_set = true;
    }

    dim3 blk(256);

    // Fused QKV projection: 16 + 4 + 4 N-tiles
    sgemm128<<<dim3(24, LQ / 128), blk>>>(x, DIM,
                                          Wq, qb, NH * HD, 16,
                                          Wk, kb, NKVH * HD, 4,
                                          Wv, vb, NKVH * HD);

    norm_rope_kernel<<<dim3(LQ, NH), blk>>>(qb, NH, q_scale, positions, 1);
    norm_rope_kernel<<<dim3(LQ, NKVH), blk>>>(kb, NKVH, k_scale, positions, 1);
    norm_rope_kernel<<<dim3(LQ, NKVH), blk>>>(vb, NKVH, (const float*)nullptr, positions, 0);

    attn_kernel<<<dim3(LQ / QT, NH), blk,
                  (QT * QPAD + HD * KTPAD + KT * QPAD + QT * SPAD) * 4>>>();

    // Output projection
    sgemm128<<<dim3(16, LQ / 128), blk>>>(ab, NH * HD,
                                          Wo, out, DIM, 16,
                                          (const float*)nullptr, (float*)nullptr, 0, 0,
                                          (const float*)nullptr, (float*)nullptr, 0);
}

// round 6
// speedup vs baseline: 3.4164x; 1.3654x over previous
#include <cuda_runtime.h>
#include <cuda_bf16.h>
#include <math.h>

#define LQ 4096
#define DIM 2048
#define NH 8
#define NKVH 2
#define HD 256
#define WIN 512

// fp32 intermediates
__device__ float g_q[(size_t)LQ * NH * HD];
__device__ float g_k[(size_t)LQ * NKVH * HD];
__device__ float g_v[(size_t)LQ * NKVH * HD];
__device__ float g_attn[(size_t)LQ * NH * HD];

// bf16 hi/lo split, k-pairs packed in uint32 (lower 16 = even k)
__device__ unsigned g_xh[(size_t)LQ * DIM / 2];
__device__ unsigned g_xl[(size_t)LQ * DIM / 2];
__device__ unsigned g_ah[(size_t)LQ * (NH * HD) / 2];
__device__ unsigned g_al[(size_t)LQ * (NH * HD) / 2];
// weights transposed to [N][K/2] packed
__device__ unsigned g_wqh[(size_t)(NH * HD) * DIM / 2];
__device__ unsigned g_wql[(size_t)(NH * HD) * DIM / 2];
__device__ unsigned g_wkh[(size_t)(NKVH * HD) * DIM / 2];
__device__ unsigned g_wkl[(size_t)(NKVH * HD) * DIM / 2];
__device__ unsigned g_wvh[(size_t)(NKVH * HD) * DIM / 2];
__device__ unsigned g_wvl[(size_t)(NKVH * HD) * DIM / 2];
__device__ unsigned g_woh[(size_t)DIM * (NH * HD) / 2];
__device__ unsigned g_wol[(size_t)DIM * (NH * HD) / 2];

__device__ __forceinline__ unsigned pack2(__nv_bfloat16 a, __nv_bfloat16 b) {
    return (unsigned)__bfloat16_as_ushort(a) | ((unsigned)__bfloat16_as_ushort(b) << 16);
}

// split fp32 pairs (contiguous) -> hi/lo packed
__global__ __launch_bounds__(256) void splitpack(const float* __restrict__ src,
                                                 unsigned* __restrict__ hi,
                                                 unsigned* __restrict__ lo,
                                                 int npairs) {
    int i = blockIdx.x * 256 + threadIdx.x;
    if (i >= npairs) return;
    float2 v = ((const float2*)src)[i];
    __nv_bfloat16 ha = __float2bfloat16_rn(v.x), hb = __float2bfloat16_rn(v.y);
    float ra = v.x - __bfloat162float(ha);
    float rb = v.y - __bfloat162float(hb);
    hi[i] = pack2(ha, hb);
    lo[i] = pack2(__float2bfloat16_rn(ra), __float2bfloat16_rn(rb));
}

// W[K][N] row-major -> Wh/Wl [N][K/2] packed (transpose + split)
__global__ __launch_bounds__(256) void wsplit(const float* __restrict__ W,
                                              unsigned* __restrict__ Wh,
                                              unsigned* __restrict__ Wl,
                                              int K, int N) {
    int idx = blockIdx.x * 256 + threadIdx.x;
    int total = N * (K >> 1);
    if (idx >= total) return;
    int i = idx / N;      // k-pair index (slow -> coalesced reads over n)
    int n = idx % N;
    float a = W[(size_t)(2 * i) * N + n];
    float b = W[(size_t)(2 * i + 1) * N + n];
    __nv_bfloat16 ha = __float2bfloat16_rn(a), hb = __float2bfloat16_rn(b);
    float ra = a - __bfloat162float(ha);
    float rb = b - __bfloat162float(hb);
    size_t o = (size_t)n * (K >> 1) + i;
    Wh[o] = pack2(ha, hb);
    Wl[o] = pack2(__float2bfloat16_rn(ra), __float2bfloat16_rn(rb));
}

__device__ __forceinline__ void mmabf(float* c, const unsigned* a, const unsigned* b) {
    asm volatile(
        "mma.sync.aligned.m16n8k16.row.col.f32.bf16.bf16.f32 "
        "{%0,%1,%2,%3},{%4,%5,%6,%7},{%8,%9},{%0,%1,%2,%3};"
        : "+f"(c[0]), "+f"(c[1]), "+f"(c[2]), "+f"(c[3])
        : "r"(a[0]), "r"(a[1]), "r"(a[2]), "r"(a[3]), "r"(b[0]), "r"(b[1]));
}

// ---------------------------------------------------------------------------
// Error-compensated bf16 GEMM: C = A*B with A,B pre-split hi/lo.
// A: [M][K/2] packed uints (row-major m, k-pairs). B: [N][K/2] packed.
// Block tile 128x128, K-tile 32 (16 pairs), cp.async double buffer.
// 8 warps, warp tile 64x32. 3 MMAs per logical mma (hh, hl, lh).
// ---------------------------------------------------------------------------
#define KTILE 32
#define KPAIR 16
#define BPAD 20            // row stride in uints; g*20+r distinct mod 32
#define SMBUF (128 * BPAD) // 2560 uints per matrix per buffer

__global__ __launch_bounds__(256) void bgemm(
    const unsigned* __restrict__ Agh, const unsigned* __restrict__ Agl, int K,
    const unsigned* __restrict__ Bh0, const unsigned* __restrict__ Bl0, float* __restrict__ C0, int N0, int t0,
    const unsigned* __restrict__ Bh1, const unsigned* __restrict__ Bl1, float* __restrict__ C1, int N1, int t1,
    const unsigned* __restrict__ Bh2, const unsigned* __restrict__ Bl2, float* __restrict__ C2, int N2) {
    extern __shared__ unsigned smu[];
    unsigned* SAh = smu;               // [2][SMBUF]
    unsigned* SAl = smu + 2 * SMBUF;
    unsigned* SBh = smu + 4 * SMBUF;
    unsigned* SBl = smu + 6 * SMBUF;

    int tid = threadIdx.x;
    int lane = tid & 31;
    int w = tid >> 5;
    int g = lane >> 2;
    int r = lane & 3;
    int m_base = (w >> 2) * 64;
    int n_base = (w & 3) * 32;

    int m0 = blockIdx.y * 128;
    int bx = blockIdx.x;
    const unsigned *Bh, *Bl; float* C; int N, n0;
    if (bx < t0)           { Bh = Bh0; Bl = Bl0; C = C0; N = N0; n0 = bx * 128; }
    else if (bx < t0 + t1) { Bh = Bh1; Bl = Bl1; C = C1; N = N1; n0 = (bx - t0) * 128; }
    else                   { Bh = Bh2; Bl = Bl2; C = C2; N = N2; n0 = (bx - t0 - t1) * 128; }

    int Kp = K >> 1;
    // fill mapping: 2 x uint4 per matrix per thread
    int frow = tid >> 1;          // 0..127
    int fcu = (tid & 1) * 8;      // 0 or 8

    unsigned smbase = (unsigned)__cvta_generic_to_shared(smu);
    const unsigned* ga = Agh + (size_t)(m0 + frow) * Kp + fcu;
    const unsigned* gal = Agl + (size_t)(m0 + frow) * Kp + fcu;
    const unsigned* gb = Bh + (size_t)(n0 + frow) * Kp + fcu;
    const unsigned* gbl = Bl + (size_t)(n0 + frow) * Kp + fcu;
    unsigned sa_off = (frow * BPAD + fcu) * 4;  // bytes

#define CPA(mat_idx, buf, goff, gptr)                                        \
    {                                                                        \
        unsigned sp = smbase + ((mat_idx)*2 + (buf)) * SMBUF * 4 + sa_off;   \
        asm volatile("cp.async.cg.shared.global [%0], [%1], 16;" ::          \
                     "r"(sp), "l"((gptr) + (goff)));                         \
        asm volatile("cp.async.cg.shared.global [%0], [%1], 16;" ::          \
                     "r"(sp + 16), "l"((gptr) + (goff) + 4));                \
    }

    float acc[4][4][4];
#pragma unroll
    for (int i = 0; i < 4; i++)
#pragma unroll
        for (int j = 0; j < 4; j++)
#pragma unroll
            for (int q = 0; q < 4; q++) acc[i][j][q] = 0.0f;

    int ntiles = K / KTILE;

    // preload tile 0
    CPA(0, 0, 0, ga); CPA(1, 0, 0, gal); CPA(2, 0, 0, gb); CPA(3, 0, 0, gbl);
    asm volatile("cp.async.commit_group;");

    for (int kt = 0; kt < ntiles; kt++) {
        int cur = kt & 1;
        bool more = (kt + 1) < ntiles;
        if (more) {
            int goff = (kt + 1) * KPAIR;
            int nb = cur ^ 1;
            CPA(0, nb, goff, ga); CPA(1, nb, goff, gal);
            CPA(2, nb, goff, gb); CPA(3, nb, goff, gbl);
            asm volatile("cp.async.commit_group;");
            asm volatile("cp.async.wait_group 1;");
        } else {
            asm volatile("cp.async.wait_group 0;");
        }
        __syncthreads();

        const unsigned* Ahb = SAh + cur * SMBUF;
        const unsigned* Alb = SAl + cur * SMBUF;
        const unsigned* Bhb = SBh + cur * SMBUF;
        const unsigned* Blb = SBl + cur * SMBUF;

#pragma unroll
        for (int ks = 0; ks < 2; ks++) {
            int kb = ks * 8 + r;
            unsigned bh[4][2], bl[4][2];
#pragma unroll
            for (int nt = 0; nt < 4; nt++) {
                int n = n_base + nt * 8 + g;
                bh[nt][0] = Bhb[n * BPAD + kb];
                bh[nt][1] = Bhb[n * BPAD + kb + 4];
                bl[nt][0] = Blb[n * BPAD + kb];
                bl[nt][1] = Blb[n * BPAD + kb + 4];
            }
#pragma unroll
            for (int mt = 0; mt < 4; mt++) {
                int m = m_base + mt * 16 + g;
                unsigned ah[4], al[4];
                ah[0] = Ahb[m * BPAD + kb];
                ah[1] = Ahb[(m + 8) * BPAD + kb];
                ah[2] = Ahb[m * BPAD + kb + 4];
                ah[3] = Ahb[(m + 8) * BPAD + kb + 4];
                al[0] = Alb[m * BPAD + kb];
                al[1] = Alb[(m + 8) * BPAD + kb];
                al[2] = Alb[m * BPAD + kb + 4];
                al[3] = Alb[(m + 8) * BPAD + kb + 4];
#pragma unroll
                for (int nt = 0; nt < 4; nt++) {
                    mmabf(acc[mt][nt], ah, bh[nt]);
                    mmabf(acc[mt][nt], ah, bl[nt]);
                    mmabf(acc[mt][nt], al, bh[nt]);
                }
            }
        }
        __syncthreads();
    }

#pragma unroll
    for (int mt = 0; mt < 4; mt++) {
        int row = m0 + m_base + mt * 16 + g;
#pragma unroll
        for (int nt = 0; nt < 4; nt++) {
            int col = n0 + n_base + nt * 8 + 2 * r;
            float2 v0 = {acc[mt][nt][0], acc[mt][nt][1]};
            float2 v1 = {acc[mt][nt][2], acc[mt][nt][3]};
            *(float2*)&C[(size_t)row * N + col] = v0;
            *(float2*)&C[(size_t)(row + 8) * N + col] = v1;
        }
    }
#undef CPA
}

// ---------------------------------------------------------------------------
// RMSNorm (+scale) (+RoPE) — unchanged, known-good.
// ---------------------------------------------------------------------------
__global__ __launch_bounds__(256) void norm_rope_kernel(float* __restrict__ buf,
                                                        int nheads,
                                                        const float* __restrict__ scale,
                                                        const int* __restrict__ positions,
                                                        int do_rope) {
    int li = blockIdx.x;
    int h = blockIdx.y;
    int tid = threadIdx.x;
    float* p = buf + ((size_t)li * nheads + h) * HD;

    float x = p[tid];
    float ss = x * x;
#pragma unroll
    for (int o = 16; o; o >>= 1) ss += __shfl_xor_sync(0xffffffffu, ss, o);
    __shared__ float red[8];
    if ((tid & 31) == 0) red[tid >> 5] = ss;
    __syncthreads();
    float tot = 0.0f;
#pragma unroll
    for (int i = 0; i < 8; i++) tot += red[i];
    float rstd = rsqrtf(tot * (1.0f / 256.0f) + 1e-6f);
    float xn = x * rstd;
    if (scale) xn *= scale[tid];

    if (!do_rope) { p[tid] = xn; return; }

    __shared__ float xs[256];
    xs[tid] = xn;
    __syncthreads();
    if (tid < 128) {
        int pos = positions[li];
        float ts = exp2f(13.287712379549449f * (float)tid * (1.0f / 128.0f));
        float su = (float)pos / ts;
        float s = sinf(su);
        float c = cosf(su);
        float x1 = xs[tid];
        float x2 = xs[tid + 128];
        p[tid] = x1 * c - x2 * s;
        p[tid + 128] = x2 * c + x1 * s;
    }
}

// ---------------------------------------------------------------------------
// Flash-style sliding-window attention — unchanged, known-good.
// ---------------------------------------------------------------------------
#define QT 64
#define KT 32
#define QPAD 260
#define KTPAD 34
#define SPAD 33

__global__ __launch_bounds__(256) void attn_kernel() {
    extern __shared__ float sm[];
    float* Qs = sm;
    float* Kt = Qs + QT * QPAD;
    float* Vs = Kt + HD * KTPAD;
    float* Ss = Vs + KT * QPAD;

    int q0 = blockIdx.x * QT;
    int h = blockIdx.y;
    int kvh = h >> 2;
    int tid = threadIdx.x;
    int lane = tid & 31;
    int w = tid >> 5;
    int tx = tid & 15;
    int ty = tid >> 4;

#pragma unroll
    for (int f = 0; f < 16; f++) {
        int id = f * 256 + tid;
        int q = id >> 6;
        int d = (id & 63) * 4;
        float4 v = *(const float4*)&g_q[((size_t)(q0 + q) * NH + h) * HD + d];
        *(float4*)&Qs[q * QPAD + d] = v;
    }

    float acc[8][8];
    float m8[8], l8[8];
#pragma unroll
    for (int i = 0; i < 8; i++) {
        m8[i] = -1e30f; l8[i] = 0.0f;
#pragma unroll
        for (int j = 0; j < 8; j++) acc[i][j] = 0.0f;
    }

    int kt0 = q0 - WIN;
    if (kt0 < 0) kt0 = 0;
    int ktend = q0 + QT;

    __syncthreads();

    for (int kt = kt0; kt < ktend; kt += KT) {
        {
            int row = tid >> 3;
            int cb = (tid & 7) * 4;
            const float* kg = g_k + ((size_t)(kt + row) * NKVH + kvh) * HD;
#pragma unroll
            for (int f = 0; f < 8; f++) {
                int col = cb + f * 32;
                float4 v = *(const float4*)(kg + col);
                Kt[(col + 0) * KTPAD + row] = v.x;
                Kt[(col + 1) * KTPAD + row] = v.y;
                Kt[(col + 2) * KTPAD + row] = v.z;
                Kt[(col + 3) * KTPAD + row] = v.w;
            }
#pragma unroll
            for (int f = 0; f < 8; f++) {
                int id = f * 256 + tid;
                int rr = id >> 6;
                int d = (id & 63) * 4;
                float4 v = *(const float4*)&g_v[((size_t)(kt + rr) * NKVH + kvh) * HD + d];
                *(float4*)&Vs[rr * QPAD + d] = v;
            }
        }
        __syncthreads();

        {
            int q4 = ty * 4;
            int k2 = tx * 2;
            float s[4][2];
#pragma unroll
            for (int i = 0; i < 4; i++) { s[i][0] = 0.f; s[i][1] = 0.f; }
            for (int d0 = 0; d0 < HD; d0 += 4) {
                float4 qv0 = *(const float4*)&Qs[(q4 + 0) * QPAD + d0];
                float4 qv1 = *(const float4*)&Qs[(q4 + 1) * QPAD + d0];
                float4 qv2 = *(const float4*)&Qs[(q4 + 2) * QPAD + d0];
                float4 qv3 = *(const float4*)&Qs[(q4 + 3) * QPAD + d0];
                float2 k0 = *(const float2*)&Kt[(d0 + 0) * KTPAD + k2];
                float2 k1 = *(const float2*)&Kt[(d0 + 1) * KTPAD + k2];
                float2 k2v = *(const float2*)&Kt[(d0 + 2) * KTPAD + k2];
                float2 k3 = *(const float2*)&Kt[(d0 + 3) * KTPAD + k2];
                float qa[4][4] = {{qv0.x, qv0.y, qv0.z, qv0.w},
                                  {qv1.x, qv1.y, qv1.z, qv1.w},
                                  {qv2.x, qv2.y, qv2.z, qv2.w},
                                  {qv3.x, qv3.y, qv3.z, qv3.w}};
                float kx[4] = {k0.x, k1.x, k2v.x, k3.x};
                float ky[4] = {k0.y, k1.y, k2v.y, k3.y};
#pragma unroll
                for (int dd = 0; dd < 4; dd++)
#pragma unroll
                    for (int i = 0; i < 4; i++) {
                        s[i][0] += qa[i][dd] * kx[dd];
                        s[i][1] += qa[i][dd] * ky[dd];
                    }
            }
#pragma unroll
            for (int i = 0; i < 4; i++)
#pragma unroll
                for (int j = 0; j < 2; j++) {
                    int qg = q0 + q4 + i;
                    int kg = kt + k2 + j;
                    bool ok = (kg <= qg) && (kg + WIN > qg);
                    Ss[(q4 + i) * SPAD + k2 + j] = ok ? s[i][j] : -1e30f;
                }
        }
        __syncthreads();

        {
            float p8[8];
#pragma unroll
            for (int q8 = 0; q8 < 8; q8++) {
                int qrow = w * 8 + q8;
                int qg = q0 + qrow;
                int kg = kt + lane;
                float s = Ss[qrow * SPAD + lane];
                float mx = s;
#pragma unroll
                for (int o = 16; o; o >>= 1) mx = fmaxf(mx, __shfl_xor_sync(0xffffffffu, mx, o));
                float mn = fmaxf(m8[q8], mx);
                bool ok = (kg <= qg) && (kg + WIN > qg);
                float p = ok ? __expf(s - mn) : 0.0f;
                float sum = p;
#pragma unroll
                for (int o = 16; o; o >>= 1) sum += __shfl_xor_sync(0xffffffffu, sum, o);
                float sc = __expf(m8[q8] - mn);
                l8[q8] = l8[q8] * sc + sum;
                m8[q8] = mn;
#pragma unroll
                for (int j = 0; j < 8; j++) acc[q8][j] *= sc;
                p8[q8] = p;
            }
#pragma unroll
            for (int k = 0; k < KT; k++) {
                float4 v0 = *(const float4*)&Vs[k * QPAD + lane * 4];
                float4 v1 = *(const float4*)&Vs[k * QPAD + 128 + lane * 4];
#pragma unroll
                for (int q8 = 0; q8 < 8; q8++) {
                    float pk = __shfl_sync(0xffffffffu, p8[q8], k);
                    acc[q8][0] += pk * v0.x; acc[q8][1] += pk * v0.y;
                    acc[q8][2] += pk * v0.z; acc[q8][3] += pk * v0.w;
                    acc[q8][4] += pk * v1.x; acc[q8][5] += pk * v1.y;
                    acc[q8][6] += pk * v1.z; acc[q8][7] += pk * v1.w;
                }
            }
        }
        __syncthreads();
    }

#pragma unroll
    for (int q8 = 0; q8 < 8; q8++) {
        int qg = q0 + w * 8 + q8;
        float inv = 1.0f / l8[q8];
        size_t base = ((size_t)qg * NH + h) * HD;
        float4 o0, o1;
        o0.x = acc[q8][0] * inv; o0.y = acc[q8][1] * inv;
        o0.z = acc[q8][2] * inv; o0.w = acc[q8][3] * inv;
        o1.x = acc[q8][4] * inv; o1.y = acc[q8][5] * inv;
        o1.z = acc[q8][6] * inv; o1.w = acc[q8][7] * inv;
        *(float4*)&g_attn[base + lane * 4] = o0;
        *(float4*)&g_attn[base + 128 + lane * 4] = o1;
    }
}

// ---------------------------------------------------------------------------
extern "C" void kernel_launch(void* const* d_in, const int* in_sizes, int n_in,
                              void* d_out, int out_size) {
    const float* x = (const float*)d_in[0];
    const int* positions = (const int*)d_in[1];
    const float* Wq = (const float*)d_in[2];
    const float* Wk = (const float*)d_in[3];
    const float* Wv = (const float*)d_in[4];
    const float* Wo = (const float*)d_in[5];
    const float* q_scale = (const float*)d_in[6];
    const float* k_scale = (const float*)d_in[7];
    float* out = (float*)d_out;

    float *qb, *kb, *vb, *ab;
    unsigned *xh, *xl, *ah, *al;
    unsigned *wqh, *wql, *wkh, *wkl, *wvh, *wvl, *woh, *wol;
    cudaGetSymbolAddress((void**)&qb, g_q);
    cudaGetSymbolAddress((void**)&kb, g_k);
    cudaGetSymbolAddress((void**)&vb, g_v);
    cudaGetSymbolAddress((void**)&ab, g_attn);
    cudaGetSymbolAddress((void**)&xh, g_xh);
    cudaGetSymbolAddress((void**)&xl, g_xl);
    cudaGetSymbolAddress((void**)&ah, g_ah);
    cudaGetSymbolAddress((void**)&al, g_al);
    cudaGetSymbolAddress((void**)&wqh, g_wqh);
    cudaGetSymbolAddress((void**)&wql, g_wql);
    cudaGetSymbolAddress((void**)&wkh, g_wkh);
    cudaGetSymbolAddress((void**)&wkl, g_wkl);
    cudaGetSymbolAddress((void**)&wvh, g_wvh);
    cudaGetSymbolAddress((void**)&wvl, g_wvl);
    cudaGetSymbolAddress((void**)&woh, g_woh);
    cudaGetSymbolAddress((void**)&wol, g_wol);

    cudaFuncSetAttribute(attn_kernel, cudaFuncAttributeMaxDynamicSharedMemorySize,
                         (QT * QPAD + HD * KTPAD + KT * QPAD + QT * SPAD) * 4);
    cudaFuncSetAttribute(bgemm, cudaFuncAttributeMaxDynamicSharedMemorySize,
                         8 * SMBUF * 4);

    dim3 blk(256);

    // splits
    {
        int np = LQ * DIM / 2;
        splitpack<<<(np + 255) / 256, blk>>>(x, xh, xl, np);
        int tq = (NH * HD) * (DIM / 2);
        wsplit<<<(tq + 255) / 256, blk>>>(Wq, wqh, wql, DIM, NH * HD);
        int tk = (NKVH * HD) * (DIM / 2);
        wsplit<<<(tk + 255) / 256, blk>>>(Wk, wkh, wkl, DIM, NKVH * HD);
        wsplit<<<(tk + 255) / 256, blk>>>(Wv, wvh, wvl, DIM, NKVH * HD);
        int to = DIM * ((NH * HD) / 2);
        wsplit<<<(to + 255) / 256, blk>>>(Wo, woh, wol, NH * HD, DIM);
    }

    // Fused QKV projection
    bgemm<<<dim3(24, LQ / 128), blk, 8 * SMBUF * 4>>>(
        xh, xl, DIM,
        wqh, wql, qb, NH * HD, 16,
        wkh, wkl, kb, NKVH * HD, 4,
        wvh, wvl, vb, NKVH * HD);

    norm_rope_kernel<<<dim3(LQ, NH), blk>>>(qb, NH, q_scale, positions, 1);
    norm_rope_kernel<<<dim3(LQ, NKVH), blk>>>(kb, NKVH, k_scale, positions, 1);
    norm_rope_kernel<<<dim3(LQ, NKVH), blk>>>(vb, NKVH, (const float*)nullptr, positions, 0);

    attn_kernel<<<dim3(LQ / QT, NH), blk,
                  (QT * QPAD + HD * KTPAD + KT * QPAD + QT * SPAD) * 4>>>();

    // split attention output, then Wo projection
    {
        int np = LQ * (NH * HD) / 2;
        splitpack<<<(np + 255) / 256, blk>>>(ab, ah, al, np);
    }
    bgemm<<<dim3(16, LQ / 128), blk, 8 * SMBUF * 4>>>(
        ah, al, NH * HD,
        woh, wol, out, DIM, 16,
        (const unsigned*)nullptr, (const unsigned*)nullptr, (float*)nullptr, 0, 0,
        (const unsigned*)nullptr, (const unsigned*)nullptr, (float*)nullptr, 0);
}

// round 11
// speedup vs baseline: 4.3276x; 1.2667x over previous
#include <cuda_runtime.h>
#include <cuda_bf16.h>
#include <math.h>

#define LQ 4096
#define DIM 2048
#define NH 8
#define NKVH 2
#define HD 256
#define WIN 512

// fp32 intermediates
__device__ float g_q[(size_t)LQ * NH * HD];
__device__ float g_k[(size_t)LQ * NKVH * HD];
__device__ float g_v[(size_t)LQ * NKVH * HD];
__device__ float g_attn[(size_t)LQ * NH * HD];

// bf16 hi/lo split, k-pairs packed in uint32 (lower 16 = even k)
__device__ unsigned g_xh[(size_t)LQ * DIM / 2];
__device__ unsigned g_xl[(size_t)LQ * DIM / 2];
__device__ unsigned g_ah[(size_t)LQ * (NH * HD) / 2];
__device__ unsigned g_al[(size_t)LQ * (NH * HD) / 2];
// weights transposed to [N][K/2] packed
__device__ unsigned g_wqh[(size_t)(NH * HD) * DIM / 2];
__device__ unsigned g_wql[(size_t)(NH * HD) * DIM / 2];
__device__ unsigned g_wkh[(size_t)(NKVH * HD) * DIM / 2];
__device__ unsigned g_wkl[(size_t)(NKVH * HD) * DIM / 2];
__device__ unsigned g_wvh[(size_t)(NKVH * HD) * DIM / 2];
__device__ unsigned g_wvl[(size_t)(NKVH * HD) * DIM / 2];
__device__ unsigned g_woh[(size_t)DIM * (NH * HD) / 2];
__device__ unsigned g_wol[(size_t)DIM * (NH * HD) / 2];
// attention operands: Q/K split packed (d-pairs), V transposed split (token-pairs)
__device__ unsigned g_qh[(size_t)LQ * NH * HD / 2];
__device__ unsigned g_ql[(size_t)LQ * NH * HD / 2];
__device__ unsigned g_kh[(size_t)LQ * NKVH * HD / 2];
__device__ unsigned g_kl[(size_t)LQ * NKVH * HD / 2];
__device__ unsigned g_vth[(size_t)NKVH * HD * LQ / 2];
__device__ unsigned g_vtl[(size_t)NKVH * HD * LQ / 2];

__device__ __forceinline__ unsigned pack2(__nv_bfloat16 a, __nv_bfloat16 b) {
    return (unsigned)__bfloat16_as_ushort(a) | ((unsigned)__bfloat16_as_ushort(b) << 16);
}

__device__ __forceinline__ void split2(float a, float b, unsigned& hi, unsigned& lo) {
    __nv_bfloat16 ha = __float2bfloat16_rn(a), hb = __float2bfloat16_rn(b);
    hi = pack2(ha, hb);
    lo = pack2(__float2bfloat16_rn(a - __bfloat162float(ha)),
               __float2bfloat16_rn(b - __bfloat162float(hb)));
}

// split fp32 pairs (contiguous) -> hi/lo packed
__global__ __launch_bounds__(256) void splitpack(const float* __restrict__ src,
                                                 unsigned* __restrict__ hi,
                                                 unsigned* __restrict__ lo,
                                                 int npairs) {
    int i = blockIdx.x * 256 + threadIdx.x;
    if (i >= npairs) return;
    float2 v = ((const float2*)src)[i];
    unsigned h, l;
    split2(v.x, v.y, h, l);
    hi[i] = h; lo[i] = l;
}

// W[K][N] row-major -> Wh/Wl [N][K/2] packed (transpose + split)
__global__ __launch_bounds__(256) void wsplit(const float* __restrict__ W,
                                              unsigned* __restrict__ Wh,
                                              unsigned* __restrict__ Wl,
                                              int K, int N) {
    int idx = blockIdx.x * 256 + threadIdx.x;
    int total = N * (K >> 1);
    if (idx >= total) return;
    int i = idx / N;
    int n = idx % N;
    float a = W[(size_t)(2 * i) * N + n];
    float b = W[(size_t)(2 * i + 1) * N + n];
    unsigned h, l;
    split2(a, b, h, l);
    size_t o = (size_t)n * (K >> 1) + i;
    Wh[o] = h; Wl[o] = l;
}

// V [token][kvh][d] -> Vt hi/lo [kvh][d][token-pair] packed
__global__ __launch_bounds__(256) void vtsplit() {
    __shared__ float t[64][65];
    int t0 = blockIdx.x * 64;
    int d0 = blockIdx.y * 64;
    int kvh = blockIdx.z;
    int tid = threadIdx.x;
#pragma unroll
    for (int i = 0; i < 4; i++) {
        int idx = tid + i * 256;
        int tt = idx >> 4;
        int dd = (idx & 15) * 4;
        float4 v = *(const float4*)&g_v[((size_t)(t0 + tt) * NKVH + kvh) * HD + d0 + dd];
        t[tt][dd] = v.x; t[tt][dd + 1] = v.y; t[tt][dd + 2] = v.z; t[tt][dd + 3] = v.w;
    }
    __syncthreads();
#pragma unroll
    for (int i = 0; i < 8; i++) {
        int idx = tid + i * 256;
        int dd = idx >> 5;
        int tp = idx & 31;
        unsigned h, l;
        split2(t[2 * tp][dd], t[2 * tp + 1][dd], h, l);
        size_t o = ((size_t)(kvh * HD + d0 + dd)) * (LQ / 2) + (t0 >> 1) + tp;
        g_vth[o] = h; g_vtl[o] = l;
    }
}

__device__ __forceinline__ void mmabf(float* c, const unsigned* a, const unsigned* b) {
    asm volatile(
        "mma.sync.aligned.m16n8k16.row.col.f32.bf16.bf16.f32 "
        "{%0,%1,%2,%3},{%4,%5,%6,%7},{%8,%9},{%0,%1,%2,%3};"
        : "+f"(c[0]), "+f"(c[1]), "+f"(c[2]), "+f"(c[3])
        : "r"(a[0]), "r"(a[1]), "r"(a[2]), "r"(a[3]), "r"(b[0]), "r"(b[1]));
}

// ---------------------------------------------------------------------------
// Error-compensated bf16 GEMM (unchanged, known-good).
// ---------------------------------------------------------------------------
#define KTILE 32
#define KPAIR 16
#define BPAD 20
#define SMBUF (128 * BPAD)

__global__ __launch_bounds__(256) void bgemm(
    const unsigned* __restrict__ Agh, const unsigned* __restrict__ Agl, int K,
    const unsigned* __restrict__ Bh0, const unsigned* __restrict__ Bl0, float* __restrict__ C0, int N0, int t0,
    const unsigned* __restrict__ Bh1, const unsigned* __restrict__ Bl1, float* __restrict__ C1, int N1, int t1,
    const unsigned* __restrict__ Bh2, const unsigned* __restrict__ Bl2, float* __restrict__ C2, int N2) {
    extern __shared__ unsigned smu[];
    unsigned* SAh = smu;
    unsigned* SAl = smu + 2 * SMBUF;
    unsigned* SBh = smu + 4 * SMBUF;
    unsigned* SBl = smu + 6 * SMBUF;

    int tid = threadIdx.x;
    int lane = tid & 31;
    int w = tid >> 5;
    int g = lane >> 2;
    int r = lane & 3;
    int m_base = (w >> 2) * 64;
    int n_base = (w & 3) * 32;

    int m0 = blockIdx.y * 128;
    int bx = blockIdx.x;
    const unsigned *Bh, *Bl; float* C; int N, n0;
    if (bx < t0)           { Bh = Bh0; Bl = Bl0; C = C0; N = N0; n0 = bx * 128; }
    else if (bx < t0 + t1) { Bh = Bh1; Bl = Bl1; C = C1; N = N1; n0 = (bx - t0) * 128; }
    else                   { Bh = Bh2; Bl = Bl2; C = C2; N = N2; n0 = (bx - t0 - t1) * 128; }

    int Kp = K >> 1;
    int frow = tid >> 1;
    int fcu = (tid & 1) * 8;

    unsigned smbase = (unsigned)__cvta_generic_to_shared(smu);
    const unsigned* ga = Agh + (size_t)(m0 + frow) * Kp + fcu;
    const unsigned* gal = Agl + (size_t)(m0 + frow) * Kp + fcu;
    const unsigned* gb = Bh + (size_t)(n0 + frow) * Kp + fcu;
    const unsigned* gbl = Bl + (size_t)(n0 + frow) * Kp + fcu;
    unsigned sa_off = (frow * BPAD + fcu) * 4;

#define CPA(mat_idx, buf, goff, gptr)                                        \
    {                                                                        \
        unsigned sp = smbase + ((mat_idx)*2 + (buf)) * SMBUF * 4 + sa_off;   \
        asm volatile("cp.async.cg.shared.global [%0], [%1], 16;" ::          \
                     "r"(sp), "l"((gptr) + (goff)));                         \
        asm volatile("cp.async.cg.shared.global [%0], [%1], 16;" ::          \
                     "r"(sp + 16), "l"((gptr) + (goff) + 4));                \
    }

    float acc[4][4][4];
#pragma unroll
    for (int i = 0; i < 4; i++)
#pragma unroll
        for (int j = 0; j < 4; j++)
#pragma unroll
            for (int q = 0; q < 4; q++) acc[i][j][q] = 0.0f;

    int ntiles = K / KTILE;

    CPA(0, 0, 0, ga); CPA(1, 0, 0, gal); CPA(2, 0, 0, gb); CPA(3, 0, 0, gbl);
    asm volatile("cp.async.commit_group;");

    for (int kt = 0; kt < ntiles; kt++) {
        int cur = kt & 1;
        bool more = (kt + 1) < ntiles;
        if (more) {
            int goff = (kt + 1) * KPAIR;
            int nb = cur ^ 1;
            CPA(0, nb, goff, ga); CPA(1, nb, goff, gal);
            CPA(2, nb, goff, gb); CPA(3, nb, goff, gbl);
            asm volatile("cp.async.commit_group;");
            asm volatile("cp.async.wait_group 1;");
        } else {
            asm volatile("cp.async.wait_group 0;");
        }
        __syncthreads();

        const unsigned* Ahb = SAh + cur * SMBUF;
        const unsigned* Alb = SAl + cur * SMBUF;
        const unsigned* Bhb = SBh + cur * SMBUF;
        const unsigned* Blb = SBl + cur * SMBUF;

#pragma unroll
        for (int ks = 0; ks < 2; ks++) {
            int kb = ks * 8 + r;
            unsigned bh[4][2], bl[4][2];
#pragma unroll
            for (int nt = 0; nt < 4; nt++) {
                int n = n_base + nt * 8 + g;
                bh[nt][0] = Bhb[n * BPAD + kb];
                bh[nt][1] = Bhb[n * BPAD + kb + 4];
                bl[nt][0] = Blb[n * BPAD + kb];
                bl[nt][1] = Blb[n * BPAD + kb + 4];
            }
#pragma unroll
            for (int mt = 0; mt < 4; mt++) {
                int m = m_base + mt * 16 + g;
                unsigned ah[4], al[4];
                ah[0] = Ahb[m * BPAD + kb];
                ah[1] = Ahb[(m + 8) * BPAD + kb];
                ah[2] = Ahb[m * BPAD + kb + 4];
                ah[3] = Ahb[(m + 8) * BPAD + kb + 4];
                al[0] = Alb[m * BPAD + kb];
                al[1] = Alb[(m + 8) * BPAD + kb];
                al[2] = Alb[m * BPAD + kb + 4];
                al[3] = Alb[(m + 8) * BPAD + kb + 4];
#pragma unroll
                for (int nt = 0; nt < 4; nt++) {
                    mmabf(acc[mt][nt], ah, bh[nt]);
                    mmabf(acc[mt][nt], ah, bl[nt]);
                    mmabf(acc[mt][nt], al, bh[nt]);
                }
            }
        }
        __syncthreads();
    }

#pragma unroll
    for (int mt = 0; mt < 4; mt++) {
        int row = m0 + m_base + mt * 16 + g;
#pragma unroll
        for (int nt = 0; nt < 4; nt++) {
            int col = n0 + n_base + nt * 8 + 2 * r;
            float2 v0 = {acc[mt][nt][0], acc[mt][nt][1]};
            float2 v1 = {acc[mt][nt][2], acc[mt][nt][3]};
            *(float2*)&C[(size_t)row * N + col] = v0;
            *(float2*)&C[(size_t)(row + 8) * N + col] = v1;
        }
    }
#undef CPA
}

// ---------------------------------------------------------------------------
// RMSNorm (+scale) (+RoPE) — unchanged, known-good.
// ---------------------------------------------------------------------------
__global__ __launch_bounds__(256) void norm_rope_kernel(float* __restrict__ buf,
                                                        int nheads,
                                                        const float* __restrict__ scale,
                                                        const int* __restrict__ positions,
                                                        int do_rope) {
    int li = blockIdx.x;
    int h = blockIdx.y;
    int tid = threadIdx.x;
    float* p = buf + ((size_t)li * nheads + h) * HD;

    float x = p[tid];
    float ss = x * x;
#pragma unroll
    for (int o = 16; o; o >>= 1) ss += __shfl_xor_sync(0xffffffffu, ss, o);
    __shared__ float red[8];
    if ((tid & 31) == 0) red[tid >> 5] = ss;
    __syncthreads();
    float tot = 0.0f;
#pragma unroll
    for (int i = 0; i < 8; i++) tot += red[i];
    float rstd = rsqrtf(tot * (1.0f / 256.0f) + 1e-6f);
    float xn = x * rstd;
    if (scale) xn *= scale[tid];

    if (!do_rope) { p[tid] = xn; return; }

    __shared__ float xs[256];
    xs[tid] = xn;
    __syncthreads();
    if (tid < 128) {
        int pos = positions[li];
        float ts = exp2f(13.287712379549449f * (float)tid * (1.0f / 128.0f));
        float su = (float)pos / ts;
        float s = sinf(su);
        float c = cosf(su);
        float x1 = xs[tid];
        float x2 = xs[tid + 128];
        p[tid] = x1 * c - x2 * s;
        p[tid + 128] = x2 * c + x1 * s;
    }
}

// ---------------------------------------------------------------------------
// Tensor-core flash attention (compensated bf16, 3-mma splits everywhere).
// Block = 64 queries x 1 head. 8 warps: 4 query-groups(16q) x 2 dim-halves(128d).
// 32-key tiles, cp.async double-buffered K/V; Q loaded once.
// Smem strides chosen so fragment LDS is bank-conflict-free.
// ---------------------------------------------------------------------------
#define AQT 64
#define AKT 32
#define QSTR 132
#define VSTR 20
// uint offsets within dynamic smem
#define OQH 0
#define OQL (64 * QSTR)                 // 8448
#define OKH (2 * 64 * QSTR)             // 16896
#define OKL (OKH + 2 * 32 * QSTR)       // 25344
#define OVH (OKL + 2 * 32 * QSTR)       // 33792
#define OVL (OVH + 2 * 256 * VSTR)      // 44032
#define ATTN_SMEM ((OVL + 2 * 256 * VSTR) * 4)  // 54272 uints = 217088 B

__global__ __launch_bounds__(256) void attn_mma() {
    extern __shared__ unsigned su[];

    int q0 = blockIdx.x * AQT;
    int h = blockIdx.y;
    int kvh = h >> 2;
    int tid = threadIdx.x;
    int lane = tid & 31;
    int w = tid >> 5;
    int g = lane >> 2;
    int r = lane & 3;
    int qgrp = w >> 1;
    int dg = w & 1;

    unsigned sb = (unsigned)__cvta_generic_to_shared(su);

#define CPA1(dstu, src)                                                     \
    asm volatile("cp.async.cg.shared.global [%0], [%1], 16;" ::             \
                 "r"(sb + (dstu) * 4), "l"(src))

    int kt0 = q0 - WIN;
    if (kt0 < 0) kt0 = 0;
    int ktend = q0 + AQT;

    // --- Q tiles (once): 8 chunks per matrix ---
#pragma unroll
    for (int i = 0; i < 8; i++) {
        int c = tid + i * 256;
        int row = c >> 5;
        int cl = (c & 31) * 4;
        size_t src = ((size_t)(q0 + row) * NH + h) * (HD / 2) + cl;
        CPA1(OQH + row * QSTR + cl, g_qh + src);
        CPA1(OQL + row * QSTR + cl, g_ql + src);
    }
    // --- K/V tile 0 ---
    {
#pragma unroll
        for (int i = 0; i < 4; i++) {
            int c = tid + i * 256;
            int row = c >> 5;
            int cl = (c & 31) * 4;
            size_t src = ((size_t)(kt0 + row) * NKVH + kvh) * (HD / 2) + cl;
            CPA1(OKH + row * QSTR + cl, g_kh + src);
            CPA1(OKL + row * QSTR + cl, g_kl + src);
        }
#pragma unroll
        for (int i = 0; i < 4; i++) {
            int c = tid + i * 256;
            int row = c >> 2;
            int cl = (c & 3) * 4;
            size_t src = ((size_t)(kvh * HD + row)) * (LQ / 2) + (kt0 >> 1) + cl;
            CPA1(OVH + row * VSTR + cl, g_vth + src);
            CPA1(OVL + row * VSTR + cl, g_vtl + src);
        }
    }
    asm volatile("cp.async.commit_group;");

    float o[16][4];
#pragma unroll
    for (int i = 0; i < 16; i++)
#pragma unroll
        for (int j = 0; j < 4; j++) o[i][j] = 0.0f;
    float m0 = -1e30f, m1 = -1e30f, l0 = 0.0f, l1 = 0.0f;

    int qg0 = q0 + qgrp * 16 + g;
    int qg1 = qg0 + 8;
    int qrow = qgrp * 16 + g;

    int buf = 0;
    for (int kt = kt0; kt < ktend; kt += AKT) {
        bool more = (kt + AKT) < ktend;
        if (more) {
            int nb = buf ^ 1;
            int ktn = kt + AKT;
#pragma unroll
            for (int i = 0; i < 4; i++) {
                int c = tid + i * 256;
                int row = c >> 5;
                int cl = (c & 31) * 4;
                size_t src = ((size_t)(ktn + row) * NKVH + kvh) * (HD / 2) + cl;
                CPA1(OKH + nb * (32 * QSTR) + row * QSTR + cl, g_kh + src);
                CPA1(OKL + nb * (32 * QSTR) + row * QSTR + cl, g_kl + src);
            }
#pragma unroll
            for (int i = 0; i < 4; i++) {
                int c = tid + i * 256;
                int row = c >> 2;
                int cl = (c & 3) * 4;
                size_t src = ((size_t)(kvh * HD + row)) * (LQ / 2) + (ktn >> 1) + cl;
                CPA1(OVH + nb * (256 * VSTR) + row * VSTR + cl, g_vth + src);
                CPA1(OVL + nb * (256 * VSTR) + row * VSTR + cl, g_vtl + src);
            }
            asm volatile("cp.async.commit_group;");
            asm volatile("cp.async.wait_group 1;");
        } else {
            asm volatile("cp.async.wait_group 0;");
        }
        __syncthreads();

        const unsigned* Qhp = su + OQH;
        const unsigned* Qlp = su + OQL;
        const unsigned* Khp = su + OKH + buf * (32 * QSTR);
        const unsigned* Klp = su + OKL + buf * (32 * QSTR);
        const unsigned* Vhp = su + OVH + buf * (256 * VSTR);
        const unsigned* Vlp = su + OVL + buf * (256 * VSTR);

        // ---- S = Q K^T (compensated) ----
        float s[4][4];
#pragma unroll
        for (int j = 0; j < 4; j++)
#pragma unroll
            for (int e = 0; e < 4; e++) s[j][e] = 0.0f;

#pragma unroll
        for (int k16 = 0; k16 < 16; k16++) {
            int ab = qrow * QSTR + k16 * 8 + r;
            unsigned ah[4], al[4];
            ah[0] = Qhp[ab];
            ah[1] = Qhp[ab + 8 * QSTR];
            ah[2] = Qhp[ab + 4];
            ah[3] = Qhp[ab + 8 * QSTR + 4];
            al[0] = Qlp[ab];
            al[1] = Qlp[ab + 8 * QSTR];
            al[2] = Qlp[ab + 4];
            al[3] = Qlp[ab + 8 * QSTR + 4];
#pragma unroll
            for (int j = 0; j < 4; j++) {
                int bb = (j * 8 + g) * QSTR + k16 * 8 + r;
                unsigned bh[2] = {Khp[bb], Khp[bb + 4]};
                unsigned bl[2] = {Klp[bb], Klp[bb + 4]};
                mmabf(s[j], ah, bh);
                mmabf(s[j], ah, bl);
                mmabf(s[j], al, bh);
            }
        }

        // ---- online softmax in fragment layout ----
        float rm0 = -1e30f, rm1 = -1e30f;
        bool ok[4][4];
#pragma unroll
        for (int j = 0; j < 4; j++) {
            int kg = kt + j * 8 + 2 * r;
            ok[j][0] = (kg <= qg0) && (kg + WIN > qg0);
            ok[j][1] = (kg + 1 <= qg0) && (kg + 1 + WIN > qg0);
            ok[j][2] = (kg <= qg1) && (kg + WIN > qg1);
            ok[j][3] = (kg + 1 <= qg1) && (kg + 1 + WIN > qg1);
            rm0 = fmaxf(rm0, ok[j][0] ? s[j][0] : -1e30f);
            rm0 = fmaxf(rm0, ok[j][1] ? s[j][1] : -1e30f);
            rm1 = fmaxf(rm1, ok[j][2] ? s[j][2] : -1e30f);
            rm1 = fmaxf(rm1, ok[j][3] ? s[j][3] : -1e30f);
        }
        rm0 = fmaxf(rm0, __shfl_xor_sync(0xffffffffu, rm0, 1));
        rm0 = fmaxf(rm0, __shfl_xor_sync(0xffffffffu, rm0, 2));
        rm1 = fmaxf(rm1, __shfl_xor_sync(0xffffffffu, rm1, 1));
        rm1 = fmaxf(rm1, __shfl_xor_sync(0xffffffffu, rm1, 2));

        float mn0 = fmaxf(m0, rm0), mn1 = fmaxf(m1, rm1);
        float e0 = __expf(m0 - mn0), e1 = __expf(m1 - mn1);
        float p[4][4];
        float rs0 = 0.0f, rs1 = 0.0f;
#pragma unroll
        for (int j = 0; j < 4; j++) {
            p[j][0] = ok[j][0] ? __expf(s[j][0] - mn0) : 0.0f;
            p[j][1] = ok[j][1] ? __expf(s[j][1] - mn0) : 0.0f;
            p[j][2] = ok[j][2] ? __expf(s[j][2] - mn1) : 0.0f;
            p[j][3] = ok[j][3] ? __expf(s[j][3] - mn1) : 0.0f;
            rs0 += p[j][0] + p[j][1];
            rs1 += p[j][2] + p[j][3];
        }
        rs0 += __shfl_xor_sync(0xffffffffu, rs0, 1);
        rs0 += __shfl_xor_sync(0xffffffffu, rs0, 2);
        rs1 += __shfl_xor_sync(0xffffffffu, rs1, 1);
        rs1 += __shfl_xor_sync(0xffffffffu, rs1, 2);
        l0 = l0 * e0 + rs0;
        l1 = l1 * e1 + rs1;
        m0 = mn0; m1 = mn1;

#pragma unroll
        for (int jn = 0; jn < 16; jn++) {
            o[jn][0] *= e0; o[jn][1] *= e0;
            o[jn][2] *= e1; o[jn][3] *= e1;
        }

        // ---- pack P hi/lo into A-fragments ----
        unsigned ph[2][4], pl[2][4];
#pragma unroll
        for (int kh2 = 0; kh2 < 2; kh2++) {
            int j0 = kh2 * 2;
            split2(p[j0][0], p[j0][1], ph[kh2][0], pl[kh2][0]);
            split2(p[j0][2], p[j0][3], ph[kh2][1], pl[kh2][1]);
            split2(p[j0 + 1][0], p[j0 + 1][1], ph[kh2][2], pl[kh2][2]);
            split2(p[j0 + 1][2], p[j0 + 1][3], ph[kh2][3], pl[kh2][3]);
        }

        // ---- O += P V (compensated) ----
#pragma unroll
        for (int jn = 0; jn < 16; jn++) {
            int d = dg * 128 + jn * 8 + g;
#pragma unroll
            for (int kh2 = 0; kh2 < 2; kh2++) {
                int vb = d * VSTR + kh2 * 8 + r;
                unsigned bh[2] = {Vhp[vb], Vhp[vb + 4]};
                unsigned bl[2] = {Vlp[vb], Vlp[vb + 4]};
                mmabf(o[jn], ph[kh2], bh);
                mmabf(o[jn], ph[kh2], bl);
                mmabf(o[jn], pl[kh2], bh);
            }
        }
        __syncthreads();
        buf ^= 1;
    }

    float inv0 = 1.0f / l0, inv1 = 1.0f / l1;
    int row0 = q0 + qgrp * 16 + g;
#pragma unroll
    for (int jn = 0; jn < 16; jn++) {
        int col = dg * 128 + jn * 8 + 2 * r;
        float2 v0 = {o[jn][0] * inv0, o[jn][1] * inv0};
        float2 v1 = {o[jn][2] * inv1, o[jn][3] * inv1};
        *(float2*)&g_attn[((size_t)row0 * NH + h) * HD + col] = v0;
        *(float2*)&g_attn[((size_t)(row0 + 8) * NH + h) * HD + col] = v1;
    }
#undef CPA1
}

// ---------------------------------------------------------------------------
extern "C" void kernel_launch(void* const* d_in, const int* in_sizes, int n_in,
                              void* d_out, int out_size) {
    const float* x = (const float*)d_in[0];
    const int* positions = (const int*)d_in[1];
    const float* Wq = (const float*)d_in[2];
    const float* Wk = (const float*)d_in[3];
    const float* Wv = (const float*)d_in[4];
    const float* Wo = (const float*)d_in[5];
    const float* q_scale = (const float*)d_in[6];
    const float* k_scale = (const float*)d_in[7];
    float* out = (float*)d_out;

    float *qb, *kb, *vb, *ab;
    unsigned *xh, *xl, *ah, *al;
    unsigned *wqh, *wql, *wkh, *wkl, *wvh, *wvl, *woh, *wol;
    unsigned *qh, *ql, *kh, *kl;
    cudaGetSymbolAddress((void**)&qb, g_q);
    cudaGetSymbolAddress((void**)&kb, g_k);
    cudaGetSymbolAddress((void**)&vb, g_v);
    cudaGetSymbolAddress((void**)&ab, g_attn);
    cudaGetSymbolAddress((void**)&xh, g_xh);
    cudaGetSymbolAddress((void**)&xl, g_xl);
    cudaGetSymbolAddress((void**)&ah, g_ah);
    cudaGetSymbolAddress((void**)&al, g_al);
    cudaGetSymbolAddress((void**)&wqh, g_wqh);
    cudaGetSymbolAddress((void**)&wql, g_wql);
    cudaGetSymbolAddress((void**)&wkh, g_wkh);
    cudaGetSymbolAddress((void**)&wkl, g_wkl);
    cudaGetSymbolAddress((void**)&wvh, g_wvh);
    cudaGetSymbolAddress((void**)&wvl, g_wvl);
    cudaGetSymbolAddress((void**)&woh, g_woh);
    cudaGetSymbolAddress((void**)&wol, g_wol);
    cudaGetSymbolAddress((void**)&qh, g_qh);
    cudaGetSymbolAddress((void**)&ql, g_ql);
    cudaGetSymbolAddress((void**)&kh, g_kh);
    cudaGetSymbolAddress((void**)&kl, g_kl);

    cudaFuncSetAttribute(bgemm, cudaFuncAttributeMaxDynamicSharedMemorySize,
                         8 * SMBUF * 4);
    cudaFuncSetAttribute(attn_mma, cudaFuncAttributeMaxDynamicSharedMemorySize,
                         ATTN_SMEM);

    dim3 blk(256);

    // input / weight splits
    {
        int np = LQ * DIM / 2;
        splitpack<<<(np + 255) / 256, blk>>>(x, xh, xl, np);
        int tq = (NH * HD) * (DIM / 2);
        wsplit<<<(tq + 255) / 256, blk>>>(Wq, wqh, wql, DIM, NH * HD);
        int tk = (NKVH * HD) * (DIM / 2);
        wsplit<<<(tk + 255) / 256, blk>>>(Wk, wkh, wkl, DIM, NKVH * HD);
        wsplit<<<(tk + 255) / 256, blk>>>(Wv, wvh, wvl, DIM, NKVH * HD);
        int to = DIM * ((NH * HD) / 2);
        wsplit<<<(to + 255) / 256, blk>>>(Wo, woh, wol, NH * HD, DIM);
    }

    // QKV projection
    bgemm<<<dim3(24, LQ / 128), blk, 8 * SMBUF * 4>>>(
        xh, xl, DIM,
        wqh, wql, qb, NH * HD, 16,
        wkh, wkl, kb, NKVH * HD, 4,
        wvh, wvl, vb, NKVH * HD);

    norm_rope_kernel<<<dim3(LQ, NH), blk>>>(qb, NH, q_scale, positions, 1);
    norm_rope_kernel<<<dim3(LQ, NKVH), blk>>>(kb, NKVH, k_scale, positions, 1);
    norm_rope_kernel<<<dim3(LQ, NKVH), blk>>>(vb, NKVH, (const float*)nullptr, positions, 0);

    // attention operand splits
    {
        int np = LQ * NH * HD / 2;
        splitpack<<<(np + 255) / 256, blk>>>(qb, qh, ql, np);
        int nk = LQ * NKVH * HD / 2;
        splitpack<<<(nk + 255) / 256, blk>>>(kb, kh, kl, nk);
        vtsplit<<<dim3(LQ / 64, HD / 64, NKVH), blk>>>();
    }

    attn_mma<<<dim3(LQ / AQT, NH), blk, ATTN_SMEM>>>();

    // output projection
    {
        int np = LQ * (NH * HD) / 2;
        splitpack<<<(np + 255) / 256, blk>>>(ab, ah, al, np);
    }
    bgemm<<<dim3(16, LQ / 128), blk, 8 * SMBUF * 4>>>(
        ah, al, NH * HD,
        woh, wol, out, DIM, 16,
        (const unsigned*)nullptr, (const unsigned*)nullptr, (float*)nullptr, 0, 0,
        (const unsigned*)nullptr, (const unsigned*)nullptr, (float*)nullptr, 0);
}